// round 5
// baseline (speedup 1.0000x reference)
#include <cuda_runtime.h>
#include <cuda_bf16.h>
#include <math.h>

#define NTOK  65536
#define NWIN  512
#define SCALE 0.17677669529663687f   // 1/sqrt(32)

// Scratch (device globals)
__device__ __nv_bfloat16 g_q[NTOK * 128];
__device__ __nv_bfloat16 g_k[NTOK * 128];
__device__ __nv_bfloat16 g_v[NTOK * 128];
__device__ __nv_bfloat16 g_o[NTOK * 128];
// Pre-transposed bf16 weights
__device__ __nv_bfloat16 g_wqkv[384 * 64];   // [a][f]
__device__ __nv_bfloat16 g_wo[64 * 128];     // [f][a]
__device__ __nv_bfloat16 g_w1[128 * 64];     // [a][f]
__device__ __nv_bfloat16 g_w2[64 * 128];     // [f][a]

__device__ __forceinline__ int x_off(int tok, int f) {
    int dd = tok & 3;
    int nn = (tok >> 2) & 3;
    int tt = (tok >> 4) & 3;
    int v  = (tok >> 6) & 1;
    int n  = (tok >> 7) & 255;
    int Tt = (tok >> 15) & 1;
    return ((((v * 8 + Tt * 4 + tt) * 1024) + (n * 4 + nn)) * 4 + dd) * 64 + f;
}

__device__ __forceinline__ unsigned pack_bf2(float a, float b) {
    __nv_bfloat162 h = __floats2bfloat162_rn(a, b);
    return *(unsigned*)&h;
}

__device__ __forceinline__ void mma_bf16(float c[4], const unsigned a[4], const unsigned b[2]) {
    asm volatile("mma.sync.aligned.m16n8k16.row.col.f32.bf16.bf16.f32 "
                 "{%0,%1,%2,%3}, {%4,%5,%6,%7}, {%8,%9}, {%0,%1,%2,%3};"
                 : "+f"(c[0]), "+f"(c[1]), "+f"(c[2]), "+f"(c[3])
                 : "r"(a[0]), "r"(a[1]), "r"(a[2]), "r"(a[3]),
                   "r"(b[0]), "r"(b[1]));
}

__device__ __forceinline__ void ldm_x4(unsigned r[4], unsigned addr) {
    asm volatile("ldmatrix.sync.aligned.m8n8.x4.shared.b16 {%0,%1,%2,%3}, [%4];"
                 : "=r"(r[0]), "=r"(r[1]), "=r"(r[2]), "=r"(r[3]) : "r"(addr));
}
__device__ __forceinline__ void ldm_x4_trans(unsigned r[4], unsigned addr) {
    asm volatile("ldmatrix.sync.aligned.m8n8.x4.trans.shared.b16 {%0,%1,%2,%3}, [%4];"
                 : "=r"(r[0]), "=r"(r[1]), "=r"(r[2]), "=r"(r[3]) : "r"(addr));
}

__device__ __forceinline__ float wsum(float v) {
#pragma unroll
    for (int o = 16; o; o >>= 1) v += __shfl_xor_sync(0xffffffffu, v, o);
    return v;
}

__device__ __forceinline__ float tanh_fast(float x) {
    float y;
    asm("tanh.approx.f32 %0, %1;" : "=f"(y) : "f"(x));
    return y;
}

// ================= Kernel 0: weight prep =================
__global__ __launch_bounds__(256) void k_prep(const float* __restrict__ Wq,
                                              const float* __restrict__ Wkv,
                                              const float* __restrict__ Wo,
                                              const float* __restrict__ W1,
                                              const float* __restrict__ W2) {
    int idx = blockIdx.x * 256 + threadIdx.x;
    if (idx < 24576) {
        int a = idx >> 6, f = idx & 63;
        float w = (a < 128) ? Wq[f * 128 + a] : Wkv[f * 256 + a - 128];
        g_wqkv[idx] = __float2bfloat16(w);
    } else if (idx < 32768) {
        int j = idx - 24576;
        int f = j >> 7, a = j & 127;
        g_wo[j] = __float2bfloat16(Wo[a * 64 + f]);
    } else if (idx < 40960) {
        int j = idx - 32768;
        int a = j >> 6, f = j & 63;
        g_w1[j] = __float2bfloat16(W1[f * 128 + a]);
    } else {
        int j = idx - 40960;
        int f = j >> 7, a = j & 127;
        g_w2[j] = __float2bfloat16(W2[a * 64 + f]);
    }
}

// ================= Kernel 1: LN1 + qkv projection =================
#define HSTR 72
__global__ __launch_bounds__(256) void k_lnproj(const float* __restrict__ x,
                                                const float* __restrict__ ln1s,
                                                const float* __restrict__ ln1b,
                                                const float* __restrict__ bkv) {
    __shared__ __align__(16) __nv_bfloat16 hs[128 * HSTR];
    int t0 = blockIdx.x * 128;
    int tid = threadIdx.x;
    int wid = tid >> 5, lane = tid & 31;
    int g = lane >> 2, tq = lane & 3;
    int nbase = wid * 48;

    // weight fragments -> registers
    unsigned wf[6][4][2];
#pragma unroll
    for (int nt = 0; nt < 6; nt++) {
        int col = nbase + nt * 8 + g;
#pragma unroll
        for (int kc = 0; kc < 4; kc++) {
            wf[nt][kc][0] = *(const unsigned*)&g_wqkv[col * 64 + kc * 16 + 2 * tq];
            wf[nt][kc][1] = *(const unsigned*)&g_wqkv[col * 64 + kc * 16 + 2 * tq + 8];
        }
    }

    // LN: 2 threads per token
    {
        int tok = tid >> 1, half = (tid & 1) * 32;
        const float* xp = &x[x_off(t0 + tok, half)];
        float v[32];
        float sum = 0.f;
#pragma unroll
        for (int i = 0; i < 8; i++) {
            float4 a = *(const float4*)(xp + 4 * i);
            v[4 * i] = a.x; v[4 * i + 1] = a.y; v[4 * i + 2] = a.z; v[4 * i + 3] = a.w;
            sum += a.x + a.y + a.z + a.w;
        }
        sum += __shfl_xor_sync(0xffffffffu, sum, 1);
        float mean = sum * (1.f / 64.f), var = 0.f;
#pragma unroll
        for (int i = 0; i < 32; i++) { float d = v[i] - mean; var += d * d; }
        var += __shfl_xor_sync(0xffffffffu, var, 1);
        float inv = rsqrtf(var * (1.f / 64.f) + 1e-5f);
#pragma unroll
        for (int i = 0; i < 32; i += 2)
            *(unsigned*)&hs[tok * HSTR + half + i] =
                pack_bf2((v[i] - mean) * inv * ln1s[half + i] + ln1b[half + i],
                         (v[i + 1] - mean) * inv * ln1s[half + i + 1] + ln1b[half + i + 1]);
    }
    __syncthreads();

    int arow = (lane & 7) + ((lane >> 3) & 1) * 8;
    int acol8 = (lane >> 4) * 8;
    unsigned hsb = (unsigned)__cvta_generic_to_shared(hs) + (arow * HSTR + acol8) * 2;

    for (int m = 0; m < 8; m++) {
        unsigned af[4][4];
        unsigned base = hsb + m * 16 * HSTR * 2;
#pragma unroll
        for (int kc = 0; kc < 4; kc++) ldm_x4(af[kc], base + kc * 32);
        int r0 = m * 16 + g;
#pragma unroll
        for (int nt = 0; nt < 6; nt++) {
            float c[4] = {0.f, 0.f, 0.f, 0.f};
#pragma unroll
            for (int kc = 0; kc < 4; kc++) mma_bf16(c, af[kc], wf[nt][kc]);
            int a0 = nbase + nt * 8 + 2 * tq;
            int row0 = t0 + r0;
            if (a0 < 128) {
                *(unsigned*)&g_q[row0 * 128 + a0]       = pack_bf2(c[0], c[1]);
                *(unsigned*)&g_q[(row0 + 8) * 128 + a0] = pack_bf2(c[2], c[3]);
            } else {
                float b0 = bkv[a0 - 128], b1 = bkv[a0 - 127];
                int cc = a0 - 128;
                if (cc < 128) {
                    *(unsigned*)&g_k[row0 * 128 + cc]       = pack_bf2(c[0] + b0, c[1] + b1);
                    *(unsigned*)&g_k[(row0 + 8) * 128 + cc] = pack_bf2(c[2] + b0, c[3] + b1);
                } else {
                    *(unsigned*)&g_v[row0 * 128 + cc - 128]       = pack_bf2(c[0] + b0, c[1] + b1);
                    *(unsigned*)&g_v[(row0 + 8) * 128 + cc - 128] = pack_bf2(c[2] + b0, c[3] + b1);
                }
            }
        }
    }
}

// ================= Kernel 2: attention (one block per window, 4 heads) =================
#define KSTR 136
__global__ __launch_bounds__(512, 1) void k_attn(const float* __restrict__ bkv) {
    __shared__ __align__(16) __nv_bfloat16 Ks[64 * KSTR];
    __shared__ __align__(16) __nv_bfloat16 Vs[64 * KSTR];

    int w = blockIdx.x;
    int Tt = w >> 8, n = w & 255;
    int tid = threadIdx.x, wid = tid >> 5, lane = tid & 31;
    int head = wid & 3, qw = wid >> 2;
    int g = lane >> 2, tq = lane & 3;

    // Q fragments from global
    unsigned qf[2][2][4];
    {
        int qbase = w * 128 + qw * 32;
#pragma unroll
        for (int m = 0; m < 2; m++) {
            const __nv_bfloat16* q0 = &g_q[(qbase + m * 16 + g) * 128 + head * 32];
            const __nv_bfloat16* q1 = q0 + 8 * 128;
#pragma unroll
            for (int kcq = 0; kcq < 2; kcq++) {
                qf[m][kcq][0] = *(const unsigned*)&q0[kcq * 16 + 2 * tq];
                qf[m][kcq][1] = *(const unsigned*)&q1[kcq * 16 + 2 * tq];
                qf[m][kcq][2] = *(const unsigned*)&q0[kcq * 16 + 2 * tq + 8];
                qf[m][kcq][3] = *(const unsigned*)&q1[kcq * 16 + 2 * tq + 8];
            }
        }
    }

    // ldmatrix per-lane addresses
    int lane7 = lane & 7, laneb = (lane >> 3) & 1, lanehi = lane >> 4;
    unsigned kaddr = (unsigned)__cvta_generic_to_shared(Ks) +
                     ((lane7 + (lanehi << 3)) * KSTR + head * 32 + (laneb << 3)) * 2;
    unsigned vaddr = (unsigned)__cvta_generic_to_shared(Vs) +
                     ((lane7 + (laneb << 3)) * KSTR + head * 32 + (lanehi << 3)) * 2;

    float O[2][4][4];
#pragma unroll
    for (int m = 0; m < 2; m++)
#pragma unroll
        for (int nt = 0; nt < 4; nt++)
#pragma unroll
            for (int i = 0; i < 4; i++) O[m][nt][i] = 0.f;
    float lr[2][2] = {{0.f, 0.f}, {0.f, 0.f}};

    int jrow = tid >> 3;          // kv row this thread loads
    int c0 = (tid & 7) * 16;      // channel base (full 128 ch)

    for (int tile = 0; tile < 8; tile++) {
        __syncthreads();
        {
            int skv = tile * 64 + jrow;
            int d2 = skv & 7, nn2 = (skv >> 3) & 3, t2 = (skv >> 5) & 7, vv = (skv >> 8) & 1;
            bool pad = (d2 < 2) || (d2 >= 6);
            int Ttp = Tt, tt;
            if (t2 < 2)       { Ttp = Tt - 1; tt = t2 + 2; }
            else if (t2 >= 6) { Ttp = Tt + 1; tt = t2 - 6; }
            else              { tt = t2 - 2; }
            if (Ttp < 0 || Ttp >= 2) pad = true;
            if (pad) {
#pragma unroll
                for (int c = 0; c < 16; c += 2) {
                    *(unsigned*)&Ks[jrow * KSTR + c0 + c] = pack_bf2(bkv[c0 + c], bkv[c0 + c + 1]);
                    *(unsigned*)&Vs[jrow * KSTR + c0 + c] = pack_bf2(bkv[128 + c0 + c], bkv[128 + c0 + c + 1]);
                }
            } else {
                int tokp = ((Ttp * 256 + n) * 128) + ((vv * 4 + tt) * 4 + nn2) * 4 + (d2 - 2);
                const uint4* kp = (const uint4*)&g_k[tokp * 128 + c0];
                const uint4* vp = (const uint4*)&g_v[tokp * 128 + c0];
                uint4 k0 = kp[0], k1 = kp[1];
                uint4 v0 = vp[0], v1 = vp[1];
                *(uint4*)&Ks[jrow * KSTR + c0]     = k0;
                *(uint4*)&Ks[jrow * KSTR + c0 + 8] = k1;
                *(uint4*)&Vs[jrow * KSTR + c0]     = v0;
                *(uint4*)&Vs[jrow * KSTR + c0 + 8] = v1;
            }
        }
        __syncthreads();

#pragma unroll
        for (int kc = 0; kc < 4; kc++) {
            unsigned kb0[4], kb1[4];
            ldm_x4(kb0, kaddr + (kc * 16 * KSTR) * 2);        // k-chunk 0, n lo+hi
            ldm_x4(kb1, kaddr + (kc * 16 * KSTR + 16) * 2);   // k-chunk 1, n lo+hi
            unsigned pf[2][4];
#pragma unroll
            for (int m = 0; m < 2; m++) {
                float cl[4] = {0.f, 0.f, 0.f, 0.f};
                float chh[4] = {0.f, 0.f, 0.f, 0.f};
                mma_bf16(cl, qf[m][0], kb0);
                mma_bf16(cl, qf[m][1], kb1);
                mma_bf16(chh, qf[m][0], kb0 + 2);
                mma_bf16(chh, qf[m][1], kb1 + 2);
                float e0 = __expf(cl[0] * SCALE), e1 = __expf(cl[1] * SCALE);
                float e2 = __expf(cl[2] * SCALE), e3 = __expf(cl[3] * SCALE);
                float f0 = __expf(chh[0] * SCALE), f1 = __expf(chh[1] * SCALE);
                float f2 = __expf(chh[2] * SCALE), f3 = __expf(chh[3] * SCALE);
                lr[m][0] += e0 + e1 + f0 + f1;
                lr[m][1] += e2 + e3 + f2 + f3;
                pf[m][0] = pack_bf2(e0, e1);
                pf[m][1] = pack_bf2(e2, e3);
                pf[m][2] = pack_bf2(f0, f1);
                pf[m][3] = pack_bf2(f2, f3);
            }
            unsigned vb0[4], vb1[4];
            ldm_x4_trans(vb0, vaddr + (kc * 16 * KSTR) * 2);       // nt 0,1
            ldm_x4_trans(vb1, vaddr + (kc * 16 * KSTR + 16) * 2);  // nt 2,3
            mma_bf16(O[0][0], pf[0], vb0);
            mma_bf16(O[1][0], pf[1], vb0);
            mma_bf16(O[0][1], pf[0], vb0 + 2);
            mma_bf16(O[1][1], pf[1], vb0 + 2);
            mma_bf16(O[0][2], pf[0], vb1);
            mma_bf16(O[1][2], pf[1], vb1);
            mma_bf16(O[0][3], pf[0], vb1 + 2);
            mma_bf16(O[1][3], pf[1], vb1 + 2);
        }
    }

#pragma unroll
    for (int m = 0; m < 2; m++) {
#pragma unroll
        for (int r = 0; r < 2; r++) {
            lr[m][r] += __shfl_xor_sync(0xffffffffu, lr[m][r], 1);
            lr[m][r] += __shfl_xor_sync(0xffffffffu, lr[m][r], 2);
        }
        float i0 = 1.f / lr[m][0], i1 = 1.f / lr[m][1];
        int sq0 = w * 128 + qw * 32 + m * 16 + g;
#pragma unroll
        for (int nt = 0; nt < 4; nt++) {
            int ch = head * 32 + nt * 8 + 2 * tq;
            *(unsigned*)&g_o[sq0 * 128 + ch]       = pack_bf2(O[m][nt][0] * i0, O[m][nt][1] * i0);
            *(unsigned*)&g_o[(sq0 + 8) * 128 + ch] = pack_bf2(O[m][nt][2] * i1, O[m][nt][3] * i1);
        }
    }
}

// ================= Kernel 3: epilogue (64-token tiles, MMA + ldmatrix) =================
#define OSTR  136
#define TSTR  68
#define H2STR 72

__global__ __launch_bounds__(256) void k_epi(const float* __restrict__ x,
                                             const float* __restrict__ bo,
                                             const float* __restrict__ gamma,
                                             const float* __restrict__ ln2s,
                                             const float* __restrict__ ln2b,
                                             const float* __restrict__ b1,
                                             const float* __restrict__ b2,
                                             const float* __restrict__ gmlp,
                                             float* __restrict__ out) {
    __shared__ __align__(16) __nv_bfloat16 osgs[64 * OSTR];
    __shared__ __align__(16) float toks[64 * TSTR];
    __shared__ __align__(16) __nv_bfloat16 h2s[64 * H2STR];

    int t0 = blockIdx.x * 64;
    int tid = threadIdx.x;
    int wid = tid >> 5, lane = tid & 31;
    int g = lane >> 2, tq = lane & 3;

    int arow = (lane & 7) + ((lane >> 3) & 1) * 8;
    int acol8 = (lane >> 4) * 8;
    unsigned osb = (unsigned)__cvta_generic_to_shared(osgs) + (arow * OSTR + acol8) * 2;
    unsigned h2b = (unsigned)__cvta_generic_to_shared(h2s) + (arow * H2STR + acol8) * 2;

    for (int i = tid; i < 64 * 64; i += 256) {
        int row = i >> 6, cp = i & 63;
        *(unsigned*)&osgs[row * OSTR + cp * 2] = ((const unsigned*)g_o)[t0 * 64 + i];
    }
    for (int i = tid; i < 64 * 64; i += 256) {
        int t = i >> 6, f = i & 63;
        toks[t * TSTR + f] = x[x_off(t0 + t, f)];
    }
    __syncthreads();

    // ---- GEMM1: upd = o @ Wo; toks += gamma*(upd+bo) ----
    {
        int fcol = wid * 8 + g;
        unsigned wf[8][2];
#pragma unroll
        for (int kc = 0; kc < 8; kc++) {
            wf[kc][0] = *(const unsigned*)&g_wo[fcol * 128 + kc * 16 + 2 * tq];
            wf[kc][1] = *(const unsigned*)&g_wo[fcol * 128 + kc * 16 + 2 * tq + 8];
        }
        int c0 = wid * 8 + 2 * tq;
        float gm0 = gamma[c0], gm1 = gamma[c0 + 1];
        float bo0 = bo[c0], bo1 = bo[c0 + 1];
        for (int m = 0; m < 4; m++) {
            float c[4] = {0.f, 0.f, 0.f, 0.f};
            unsigned base = osb + m * 16 * OSTR * 2;
#pragma unroll
            for (int kc = 0; kc < 8; kc++) {
                unsigned af[4];
                ldm_x4(af, base + kc * 32);
                mma_bf16(c, af, wf[kc]);
            }
            int r0 = m * 16 + g;
            toks[r0 * TSTR + c0]           += gm0 * (c[0] + bo0);
            toks[r0 * TSTR + c0 + 1]       += gm1 * (c[1] + bo1);
            toks[(r0 + 8) * TSTR + c0]     += gm0 * (c[2] + bo0);
            toks[(r0 + 8) * TSTR + c0 + 1] += gm1 * (c[3] + bo1);
        }
    }
    __syncthreads();

    // ---- LN2 (8 rows per warp) ----
    {
        float s0 = ln2s[lane], s1 = ln2s[lane + 32];
        float bb0 = ln2b[lane], bb1 = ln2b[lane + 32];
#pragma unroll
        for (int k = 0; k < 8; k++) {
            int t = wid * 8 + k;
            float a0 = toks[t * TSTR + lane], a1 = toks[t * TSTR + lane + 32];
            float mm = wsum(a0 + a1) * (1.f / 64.f);
            float d0 = a0 - mm, d1 = a1 - mm;
            float var = wsum(d0 * d0 + d1 * d1) * (1.f / 64.f);
            float inv = rsqrtf(var + 1e-5f);
            h2s[t * H2STR + lane]      = __float2bfloat16(d0 * inv * s0 + bb0);
            h2s[t * H2STR + lane + 32] = __float2bfloat16(d1 * inv * s1 + bb1);
        }
    }
    __syncthreads();

    // ---- GEMM2: hidden = gelu(h2 @ W1 + b1) -> osgs ----
    {
        unsigned wf[2][4][2];
        float bb[2][2];
#pragma unroll
        for (int nt = 0; nt < 2; nt++) {
            int acol = wid * 16 + nt * 8 + g;
#pragma unroll
            for (int kc = 0; kc < 4; kc++) {
                wf[nt][kc][0] = *(const unsigned*)&g_w1[acol * 64 + kc * 16 + 2 * tq];
                wf[nt][kc][1] = *(const unsigned*)&g_w1[acol * 64 + kc * 16 + 2 * tq + 8];
            }
            bb[nt][0] = b1[wid * 16 + nt * 8 + 2 * tq];
            bb[nt][1] = b1[wid * 16 + nt * 8 + 2 * tq + 1];
        }
        for (int m = 0; m < 4; m++) {
            unsigned af[4][4];
            unsigned base = h2b + m * 16 * H2STR * 2;
#pragma unroll
            for (int kc = 0; kc < 4; kc++) ldm_x4(af[kc], base + kc * 32);
            int r0 = m * 16 + g;
#pragma unroll
            for (int nt = 0; nt < 2; nt++) {
                float c[4] = {0.f, 0.f, 0.f, 0.f};
#pragma unroll
                for (int kc = 0; kc < 4; kc++) mma_bf16(c, af[kc], wf[nt][kc]);
                float gz[4];
#pragma unroll
                for (int i = 0; i < 4; i++) {
                    float z = c[i] + bb[nt][i & 1];
                    float u = 0.7978845608028654f * (z + 0.044715f * z * z * z);
                    gz[i] = 0.5f * z * (1.f + tanh_fast(u));
                }
                int col = wid * 16 + nt * 8 + 2 * tq;
                *(unsigned*)&osgs[r0 * OSTR + col]       = pack_bf2(gz[0], gz[1]);
                *(unsigned*)&osgs[(r0 + 8) * OSTR + col] = pack_bf2(gz[2], gz[3]);
            }
        }
    }
    __syncthreads();

    // ---- GEMM3: out = toks + gmlp*(hidden @ W2 + b2), transposed store ----
    {
        int fcol = wid * 8 + g;
        unsigned wf[8][2];
#pragma unroll
        for (int kc = 0; kc < 8; kc++) {
            wf[kc][0] = *(const unsigned*)&g_w2[fcol * 128 + kc * 16 + 2 * tq];
            wf[kc][1] = *(const unsigned*)&g_w2[fcol * 128 + kc * 16 + 2 * tq + 8];
        }
        int c0 = wid * 8 + 2 * tq;
        float gm0 = gmlp[c0], gm1 = gmlp[c0 + 1];
        float b20 = b2[c0], b21 = b2[c0 + 1];
        for (int m = 0; m < 4; m++) {
            float c[4] = {0.f, 0.f, 0.f, 0.f};
            unsigned base = osb + m * 16 * OSTR * 2;
#pragma unroll
            for (int kc = 0; kc < 8; kc++) {
                unsigned af[4];
                ldm_x4(af, base + kc * 32);
                mma_bf16(c, af, wf[kc]);
            }
            int r0 = m * 16 + g;
            int tokA = t0 + r0, tokB = t0 + r0 + 8;
            float2 vA = make_float2(toks[r0 * TSTR + c0] + gm0 * (c[0] + b20),
                                    toks[r0 * TSTR + c0 + 1] + gm1 * (c[1] + b21));
            float2 vB = make_float2(toks[(r0 + 8) * TSTR + c0] + gm0 * (c[2] + b20),
                                    toks[(r0 + 8) * TSTR + c0 + 1] + gm1 * (c[3] + b21));
            *(float2*)&out[x_off(tokA, c0)] = vA;
            *(float2*)&out[x_off(tokB, c0)] = vB;
        }
    }
}

extern "C" void kernel_launch(void* const* d_in, const int* in_sizes, int n_in,
                              void* d_out, int out_size) {
    const float* x     = (const float*)d_in[0];
    const float* ln1_s = (const float*)d_in[1];
    const float* ln1_b = (const float*)d_in[2];
    const float* Wq    = (const float*)d_in[3];
    const float* Wkv   = (const float*)d_in[4];
    const float* bkv   = (const float*)d_in[5];
    const float* Wo    = (const float*)d_in[6];
    const float* bo    = (const float*)d_in[7];
    const float* gamma = (const float*)d_in[8];
    const float* ln2s  = (const float*)d_in[9];
    const float* ln2b  = (const float*)d_in[10];
    const float* W1    = (const float*)d_in[11];
    const float* b1    = (const float*)d_in[12];
    const float* W2    = (const float*)d_in[13];
    const float* b2    = (const float*)d_in[14];
    const float* gmlp  = (const float*)d_in[15];
    float* out = (float*)d_out;

    k_prep  <<<192, 256>>>(Wq, Wkv, Wo, W1, W2);
    k_lnproj<<<NTOK / 128, 256>>>(x, ln1_s, ln1_b, bkv);
    k_attn  <<<NWIN, 512>>>(bkv);
    k_epi   <<<NTOK / 64, 256>>>(x, bo, gamma, ln2s, ln2b, b1, b2, gmlp, out);
}

// round 6
// speedup vs baseline: 1.1376x; 1.1376x over previous
#include <cuda_runtime.h>
#include <cuda_bf16.h>
#include <math.h>

#define NTOK  65536
#define NWIN  512
#define NHEAD 4
#define SCALE 0.17677669529663687f   // 1/sqrt(32)

// Scratch (device globals)
__device__ __nv_bfloat16 g_q[NTOK * 128];
__device__ __nv_bfloat16 g_k[NTOK * 128];
__device__ __nv_bfloat16 g_v[NTOK * 128];
__device__ __nv_bfloat16 g_o[NTOK * 128];
// Pre-transposed bf16 weights
__device__ __nv_bfloat16 g_wqkv[384 * 64];   // [a][f]
__device__ __nv_bfloat16 g_wo[64 * 128];     // [f][a]
__device__ __nv_bfloat16 g_w1[128 * 64];     // [a][f]
__device__ __nv_bfloat16 g_w2[64 * 128];     // [f][a]

__device__ __forceinline__ int x_off(int tok, int f) {
    int dd = tok & 3;
    int nn = (tok >> 2) & 3;
    int tt = (tok >> 4) & 3;
    int v  = (tok >> 6) & 1;
    int n  = (tok >> 7) & 255;
    int Tt = (tok >> 15) & 1;
    return ((((v * 8 + Tt * 4 + tt) * 1024) + (n * 4 + nn)) * 4 + dd) * 64 + f;
}

__device__ __forceinline__ unsigned pack_bf2(float a, float b) {
    __nv_bfloat162 h = __floats2bfloat162_rn(a, b);
    return *(unsigned*)&h;
}

__device__ __forceinline__ void mma_bf16(float c[4], const unsigned a[4], const unsigned b[2]) {
    asm volatile("mma.sync.aligned.m16n8k16.row.col.f32.bf16.bf16.f32 "
                 "{%0,%1,%2,%3}, {%4,%5,%6,%7}, {%8,%9}, {%0,%1,%2,%3};"
                 : "+f"(c[0]), "+f"(c[1]), "+f"(c[2]), "+f"(c[3])
                 : "r"(a[0]), "r"(a[1]), "r"(a[2]), "r"(a[3]),
                   "r"(b[0]), "r"(b[1]));
}

__device__ __forceinline__ float wsum(float v) {
#pragma unroll
    for (int o = 16; o; o >>= 1) v += __shfl_xor_sync(0xffffffffu, v, o);
    return v;
}

__device__ __forceinline__ float tanh_fast(float x) {
    float y;
    asm("tanh.approx.f32 %0, %1;" : "=f"(y) : "f"(x));
    return y;
}

// ================= Kernel 0: weight prep (fp32 -> transposed bf16) =================
__global__ __launch_bounds__(256) void k_prep(const float* __restrict__ Wq,
                                              const float* __restrict__ Wkv,
                                              const float* __restrict__ Wo,
                                              const float* __restrict__ W1,
                                              const float* __restrict__ W2) {
    int idx = blockIdx.x * 256 + threadIdx.x;   // 0 .. 49151
    if (idx < 24576) {
        int a = idx >> 6, f = idx & 63;
        float w = (a < 128) ? Wq[f * 128 + a] : Wkv[f * 256 + a - 128];
        g_wqkv[idx] = __float2bfloat16(w);
    } else if (idx < 32768) {
        int j = idx - 24576;
        int f = j >> 7, a = j & 127;
        g_wo[j] = __float2bfloat16(Wo[a * 64 + f]);
    } else if (idx < 40960) {
        int j = idx - 32768;
        int a = j >> 6, f = j & 63;
        g_w1[j] = __float2bfloat16(W1[f * 128 + a]);
    } else {
        int j = idx - 40960;
        int f = j >> 7, a = j & 127;
        g_w2[j] = __float2bfloat16(W2[a * 64 + f]);
    }
}

// ================= Kernel 1: LN1 + qkv projection (MMA, W in registers) =================
#define HSTR 72
__global__ __launch_bounds__(256) void k_lnproj(const float* __restrict__ x,
                                                const float* __restrict__ ln1s,
                                                const float* __restrict__ ln1b,
                                                const float* __restrict__ bkv) {
    __shared__ __nv_bfloat16 hs[128 * HSTR];
    int t0 = blockIdx.x * 128;
    int tid = threadIdx.x;
    int wid = tid >> 5, lane = tid & 31;
    int g = lane >> 2, tq = lane & 3;
    int nbase = wid * 48;

    // B fragments (weights) -> registers, L1-hot
    unsigned wf[6][4][2];
#pragma unroll
    for (int nt = 0; nt < 6; nt++) {
        int col = nbase + nt * 8 + g;
#pragma unroll
        for (int kc = 0; kc < 4; kc++) {
            wf[nt][kc][0] = *(const unsigned*)&g_wqkv[col * 64 + kc * 16 + 2 * tq];
            wf[nt][kc][1] = *(const unsigned*)&g_wqkv[col * 64 + kc * 16 + 2 * tq + 8];
        }
    }

    if (tid < 128) {
        const float* xp = &x[x_off(t0 + tid, 0)];
        float v[64];
        float sum = 0.f;
#pragma unroll
        for (int i = 0; i < 16; i++) {
            float4 a = *(const float4*)(xp + 4 * i);
            v[4 * i] = a.x; v[4 * i + 1] = a.y; v[4 * i + 2] = a.z; v[4 * i + 3] = a.w;
            sum += a.x + a.y + a.z + a.w;
        }
        float mean = sum * (1.f / 64.f), var = 0.f;
#pragma unroll
        for (int i = 0; i < 64; i++) { float d = v[i] - mean; var += d * d; }
        float inv = rsqrtf(var * (1.f / 64.f) + 1e-5f);
#pragma unroll
        for (int i = 0; i < 64; i++)
            hs[tid * HSTR + i] = __float2bfloat16((v[i] - mean) * inv * ln1s[i] + ln1b[i]);
    }
    __syncthreads();

    for (int m = 0; m < 8; m++) {
        unsigned af[4][4];
        int r0 = m * 16 + g;
#pragma unroll
        for (int kc = 0; kc < 4; kc++) {
            af[kc][0] = *(const unsigned*)&hs[r0 * HSTR + kc * 16 + 2 * tq];
            af[kc][1] = *(const unsigned*)&hs[(r0 + 8) * HSTR + kc * 16 + 2 * tq];
            af[kc][2] = *(const unsigned*)&hs[r0 * HSTR + kc * 16 + 2 * tq + 8];
            af[kc][3] = *(const unsigned*)&hs[(r0 + 8) * HSTR + kc * 16 + 2 * tq + 8];
        }
#pragma unroll
        for (int nt = 0; nt < 6; nt++) {
            float c[4] = {0.f, 0.f, 0.f, 0.f};
#pragma unroll
            for (int kc = 0; kc < 4; kc++) mma_bf16(c, af[kc], wf[nt][kc]);
            int a0 = nbase + nt * 8 + 2 * tq;
            int row0 = t0 + m * 16 + g;
            if (a0 < 128) {
                *(unsigned*)&g_q[row0 * 128 + a0]       = pack_bf2(c[0], c[1]);
                *(unsigned*)&g_q[(row0 + 8) * 128 + a0] = pack_bf2(c[2], c[3]);
            } else {
                float b0 = bkv[a0 - 128], b1 = bkv[a0 - 127];
                int cc = a0 - 128;
                if (cc < 128) {
                    *(unsigned*)&g_k[row0 * 128 + cc]       = pack_bf2(c[0] + b0, c[1] + b1);
                    *(unsigned*)&g_k[(row0 + 8) * 128 + cc] = pack_bf2(c[2] + b0, c[3] + b1);
                } else {
                    *(unsigned*)&g_v[row0 * 128 + cc - 128]       = pack_bf2(c[0] + b0, c[1] + b1);
                    *(unsigned*)&g_v[(row0 + 8) * 128 + cc - 128] = pack_bf2(c[2] + b0, c[3] + b1);
                }
            }
        }
    }
}

// ================= Kernel 2: attention (register flash, no-max softmax) =================
#define KSTR 40
#define VSTR 72
__global__ __launch_bounds__(128) void k_attn(const float* __restrict__ bkv) {
    __shared__ __nv_bfloat16 Ks[64 * KSTR];
    __shared__ __nv_bfloat16 Vt[32 * VSTR];   // Vt[ch][kv]

    int w = blockIdx.x >> 2, head = blockIdx.x & 3;
    int Tt = w >> 8, n = w & 255;
    int tid = threadIdx.x, wid = tid >> 5, lane = tid & 31;
    int g = lane >> 2, tq = lane & 3;

    // Q fragments direct from global
    unsigned qf[2][2][4];
    {
        int base = w * 128 + wid * 32;
#pragma unroll
        for (int m = 0; m < 2; m++) {
            const __nv_bfloat16* q0 = &g_q[(base + m * 16 + g) * 128 + head * 32];
            const __nv_bfloat16* q1 = &g_q[(base + m * 16 + g + 8) * 128 + head * 32];
#pragma unroll
            for (int kc = 0; kc < 2; kc++) {
                qf[m][kc][0] = *(const unsigned*)&q0[kc * 16 + 2 * tq];
                qf[m][kc][1] = *(const unsigned*)&q1[kc * 16 + 2 * tq];
                qf[m][kc][2] = *(const unsigned*)&q0[kc * 16 + 2 * tq + 8];
                qf[m][kc][3] = *(const unsigned*)&q1[kc * 16 + 2 * tq + 8];
            }
        }
    }

    float O[2][4][4];
#pragma unroll
    for (int m = 0; m < 2; m++)
#pragma unroll
        for (int nt = 0; nt < 4; nt++)
#pragma unroll
            for (int i = 0; i < 4; i++) O[m][nt][i] = 0.f;
    float lr[2][2] = {{0.f, 0.f}, {0.f, 0.f}};

    int jrow = tid >> 1, halfc = (tid & 1) * 16;

    for (int tile = 0; tile < 8; tile++) {
        __syncthreads();
        // ---- load 64 kv rows with halo decode; V transposed ----
        {
            int skv = tile * 64 + jrow;
            int d2 = skv & 7, nn2 = (skv >> 3) & 3, t2 = (skv >> 5) & 7, vv = (skv >> 8) & 1;
            bool pad = (d2 < 2) || (d2 >= 6);
            int Ttp = Tt, tt;
            if (t2 < 2)       { Ttp = Tt - 1; tt = t2 + 2; }
            else if (t2 >= 6) { Ttp = Tt + 1; tt = t2 - 6; }
            else              { tt = t2 - 2; }
            if (Ttp < 0 || Ttp >= 2) pad = true;
            if (pad) {
#pragma unroll
                for (int c = 0; c < 16; c++) {
                    Ks[jrow * KSTR + halfc + c]   = __float2bfloat16(bkv[head * 32 + halfc + c]);
                    Vt[(halfc + c) * VSTR + jrow] = __float2bfloat16(bkv[128 + head * 32 + halfc + c]);
                }
            } else {
                int tokp = ((Ttp * 256 + n) * 128) + ((vv * 4 + tt) * 4 + nn2) * 4 + (d2 - 2);
                const __nv_bfloat16* kp = &g_k[tokp * 128 + head * 32 + halfc];
                const __nv_bfloat16* vp = &g_v[tokp * 128 + head * 32 + halfc];
#pragma unroll
                for (int c = 0; c < 16; c += 2)
                    *(unsigned*)&Ks[jrow * KSTR + halfc + c] = *(const unsigned*)&kp[c];
#pragma unroll
                for (int c = 0; c < 16; c++)
                    Vt[(halfc + c) * VSTR + jrow] = vp[c];
            }
        }
        __syncthreads();

#pragma unroll
        for (int kc = 0; kc < 4; kc++) {
            // S fragments for kv columns kc*16 .. kc*16+15 (two 8-wide tiles)
            unsigned bl[2][2], bh[2][2];
#pragma unroll
            for (int c2 = 0; c2 < 2; c2++) {
                bl[c2][0] = *(const unsigned*)&Ks[(kc * 16 + g) * KSTR + c2 * 16 + 2 * tq];
                bl[c2][1] = *(const unsigned*)&Ks[(kc * 16 + g) * KSTR + c2 * 16 + 2 * tq + 8];
                bh[c2][0] = *(const unsigned*)&Ks[(kc * 16 + 8 + g) * KSTR + c2 * 16 + 2 * tq];
                bh[c2][1] = *(const unsigned*)&Ks[(kc * 16 + 8 + g) * KSTR + c2 * 16 + 2 * tq + 8];
            }
            unsigned pf[2][4];
#pragma unroll
            for (int m = 0; m < 2; m++) {
                float cl[4] = {0.f, 0.f, 0.f, 0.f};
                float ch[4] = {0.f, 0.f, 0.f, 0.f};
#pragma unroll
                for (int c2 = 0; c2 < 2; c2++) {
                    mma_bf16(cl, qf[m][c2], bl[c2]);
                    mma_bf16(ch, qf[m][c2], bh[c2]);
                }
                float e0 = __expf(cl[0] * SCALE), e1 = __expf(cl[1] * SCALE);
                float e2 = __expf(cl[2] * SCALE), e3 = __expf(cl[3] * SCALE);
                float f0 = __expf(ch[0] * SCALE), f1 = __expf(ch[1] * SCALE);
                float f2 = __expf(ch[2] * SCALE), f3 = __expf(ch[3] * SCALE);
                lr[m][0] += e0 + e1 + f0 + f1;
                lr[m][1] += e2 + e3 + f2 + f3;
                pf[m][0] = pack_bf2(e0, e1);
                pf[m][1] = pack_bf2(e2, e3);
                pf[m][2] = pack_bf2(f0, f1);
                pf[m][3] = pack_bf2(f2, f3);
            }
            // O += P V
#pragma unroll
            for (int nt = 0; nt < 4; nt++) {
                unsigned vf[2];
                vf[0] = *(const unsigned*)&Vt[(nt * 8 + g) * VSTR + kc * 16 + 2 * tq];
                vf[1] = *(const unsigned*)&Vt[(nt * 8 + g) * VSTR + kc * 16 + 2 * tq + 8];
                mma_bf16(O[0][nt], pf[0], vf);
                mma_bf16(O[1][nt], pf[1], vf);
            }
        }
    }

    // finish: quad-reduce row sums, normalize, store bf16
#pragma unroll
    for (int m = 0; m < 2; m++) {
#pragma unroll
        for (int r = 0; r < 2; r++) {
            lr[m][r] += __shfl_xor_sync(0xffffffffu, lr[m][r], 1);
            lr[m][r] += __shfl_xor_sync(0xffffffffu, lr[m][r], 2);
        }
        float i0 = 1.f / lr[m][0], i1 = 1.f / lr[m][1];
        int sq0 = w * 128 + wid * 32 + m * 16 + g;
#pragma unroll
        for (int nt = 0; nt < 4; nt++) {
            int ch = head * 32 + nt * 8 + 2 * tq;
            *(unsigned*)&g_o[sq0 * 128 + ch]       = pack_bf2(O[m][nt][0] * i0, O[m][nt][1] * i0);
            *(unsigned*)&g_o[(sq0 + 8) * 128 + ch] = pack_bf2(O[m][nt][2] * i1, O[m][nt][3] * i1);
        }
    }
}

// ================= Kernel 3: epilogue (MMA, 128-token tile, 512 threads) =================
#define OSTR  136   // bf16 stride for os/gs buffer
#define TSTR  68    // fp32 stride for toks
#define H2STR 72
#define EPI_SMEM (128 * OSTR * 2 + 128 * TSTR * 4 + 128 * H2STR * 2)

__global__ __launch_bounds__(512) void k_epi(const float* __restrict__ x,
                                             const float* __restrict__ bo,
                                             const float* __restrict__ gamma,
                                             const float* __restrict__ ln2s,
                                             const float* __restrict__ ln2b,
                                             const float* __restrict__ b1,
                                             const float* __restrict__ b2,
                                             const float* __restrict__ gmlp,
                                             float* __restrict__ out) {
    extern __shared__ __align__(16) char smbase[];
    __nv_bfloat16* osgs = (__nv_bfloat16*)smbase;                          // [128][OSTR]
    float* toks = (float*)(smbase + 128 * OSTR * 2);                       // [128][TSTR]
    __nv_bfloat16* h2s = (__nv_bfloat16*)(smbase + 128 * OSTR * 2 + 128 * TSTR * 4);

    int t0 = blockIdx.x * 128;
    int tid = threadIdx.x;
    int wid = tid >> 5, lane = tid & 31;
    int g = lane >> 2, tq = lane & 3;
    int w8 = wid & 7, mhalf = wid >> 3;   // 8 warp-groups x 2 m-halves

    // load o (bf16, uint4 = 8 values) and x (fp32, float4)
    for (int i = tid; i < 128 * 16; i += 512) {
        int row = i >> 4, c8 = (i & 15) * 8;
        *(uint4*)&osgs[row * OSTR + c8] = ((const uint4*)g_o)[t0 * 16 + i];
    }
    for (int i = tid; i < 128 * 16; i += 512) {
        int t = i >> 4, f = (i & 15) * 4;
        *(float4*)&toks[t * TSTR + f] = *(const float4*)&x[x_off(t0 + t, f)];
    }
    __syncthreads();

    // ---- GEMM1: upd = o @ Wo; toks += gamma*(upd+bo) ----
    {
        int fcol = w8 * 8 + g;
        unsigned wf[8][2];
#pragma unroll
        for (int kc = 0; kc < 8; kc++) {
            wf[kc][0] = *(const unsigned*)&g_wo[fcol * 128 + kc * 16 + 2 * tq];
            wf[kc][1] = *(const unsigned*)&g_wo[fcol * 128 + kc * 16 + 2 * tq + 8];
        }
        int c0 = w8 * 8 + 2 * tq;
        float gm0 = gamma[c0], gm1 = gamma[c0 + 1];
        float bo0 = bo[c0], bo1 = bo[c0 + 1];
        for (int m = 0; m < 4; m++) {
            float c[4] = {0.f, 0.f, 0.f, 0.f};
            int r0 = (mhalf * 4 + m) * 16 + g;
#pragma unroll
            for (int kc = 0; kc < 8; kc++) {
                unsigned af[4];
                af[0] = *(const unsigned*)&osgs[r0 * OSTR + kc * 16 + 2 * tq];
                af[1] = *(const unsigned*)&osgs[(r0 + 8) * OSTR + kc * 16 + 2 * tq];
                af[2] = *(const unsigned*)&osgs[r0 * OSTR + kc * 16 + 2 * tq + 8];
                af[3] = *(const unsigned*)&osgs[(r0 + 8) * OSTR + kc * 16 + 2 * tq + 8];
                mma_bf16(c, af, wf[kc]);
            }
            toks[r0 * TSTR + c0]           += gm0 * (c[0] + bo0);
            toks[r0 * TSTR + c0 + 1]       += gm1 * (c[1] + bo1);
            toks[(r0 + 8) * TSTR + c0]     += gm0 * (c[2] + bo0);
            toks[(r0 + 8) * TSTR + c0 + 1] += gm1 * (c[3] + bo1);
        }
    }
    __syncthreads();

    // ---- LN2 (16 warps x 8 rows) ----
    {
        float s0 = ln2s[lane], s1 = ln2s[lane + 32];
        float bb0 = ln2b[lane], bb1 = ln2b[lane + 32];
#pragma unroll
        for (int k = 0; k < 8; k++) {
            int t = wid * 8 + k;
            float a0 = toks[t * TSTR + lane], a1 = toks[t * TSTR + lane + 32];
            float mm = wsum(a0 + a1) * (1.f / 64.f);
            float d0 = a0 - mm, d1 = a1 - mm;
            float var = wsum(d0 * d0 + d1 * d1) * (1.f / 64.f);
            float inv = rsqrtf(var + 1e-5f);
            h2s[t * H2STR + lane]      = __float2bfloat16(d0 * inv * s0 + bb0);
            h2s[t * H2STR + lane + 32] = __float2bfloat16(d1 * inv * s1 + bb1);
        }
    }
    __syncthreads();

    // ---- GEMM2: hidden = gelu(h2 @ W1 + b1) -> osgs (reused) ----
    {
        unsigned wf[2][4][2];
        float bb[2][2];
#pragma unroll
        for (int nt = 0; nt < 2; nt++) {
            int acol = w8 * 16 + nt * 8 + g;
#pragma unroll
            for (int kc = 0; kc < 4; kc++) {
                wf[nt][kc][0] = *(const unsigned*)&g_w1[acol * 64 + kc * 16 + 2 * tq];
                wf[nt][kc][1] = *(const unsigned*)&g_w1[acol * 64 + kc * 16 + 2 * tq + 8];
            }
            bb[nt][0] = b1[w8 * 16 + nt * 8 + 2 * tq];
            bb[nt][1] = b1[w8 * 16 + nt * 8 + 2 * tq + 1];
        }
        for (int m = 0; m < 4; m++) {
            int r0 = (mhalf * 4 + m) * 16 + g;
            unsigned af[4][4];
#pragma unroll
            for (int kc = 0; kc < 4; kc++) {
                af[kc][0] = *(const unsigned*)&h2s[r0 * H2STR + kc * 16 + 2 * tq];
                af[kc][1] = *(const unsigned*)&h2s[(r0 + 8) * H2STR + kc * 16 + 2 * tq];
                af[kc][2] = *(const unsigned*)&h2s[r0 * H2STR + kc * 16 + 2 * tq + 8];
                af[kc][3] = *(const unsigned*)&h2s[(r0 + 8) * H2STR + kc * 16 + 2 * tq + 8];
            }
#pragma unroll
            for (int nt = 0; nt < 2; nt++) {
                float c[4] = {0.f, 0.f, 0.f, 0.f};
#pragma unroll
                for (int kc = 0; kc < 4; kc++) mma_bf16(c, af[kc], wf[nt][kc]);
                float gz[4];
#pragma unroll
                for (int i = 0; i < 4; i++) {
                    float z = c[i] + bb[nt][i & 1];
                    float u = 0.7978845608028654f * (z + 0.044715f * z * z * z);
                    gz[i] = 0.5f * z * (1.f + tanh_fast(u));
                }
                int col = w8 * 16 + nt * 8 + 2 * tq;
                *(unsigned*)&osgs[r0 * OSTR + col]       = pack_bf2(gz[0], gz[1]);
                *(unsigned*)&osgs[(r0 + 8) * OSTR + col] = pack_bf2(gz[2], gz[3]);
            }
        }
    }
    __syncthreads();

    // ---- GEMM3: out = toks + gmlp*(hidden @ W2 + b2), transposed store ----
    {
        int fcol = w8 * 8 + g;
        unsigned wf[8][2];
#pragma unroll
        for (int kc = 0; kc < 8; kc++) {
            wf[kc][0] = *(const unsigned*)&g_w2[fcol * 128 + kc * 16 + 2 * tq];
            wf[kc][1] = *(const unsigned*)&g_w2[fcol * 128 + kc * 16 + 2 * tq + 8];
        }
        int c0 = w8 * 8 + 2 * tq;
        float gm0 = gmlp[c0], gm1 = gmlp[c0 + 1];
        float b20 = b2[c0], b21 = b2[c0 + 1];
        for (int m = 0; m < 4; m++) {
            float c[4] = {0.f, 0.f, 0.f, 0.f};
            int r0 = (mhalf * 4 + m) * 16 + g;
#pragma unroll
            for (int kc = 0; kc < 8; kc++) {
                unsigned af[4];
                af[0] = *(const unsigned*)&osgs[r0 * OSTR + kc * 16 + 2 * tq];
                af[1] = *(const unsigned*)&osgs[(r0 + 8) * OSTR + kc * 16 + 2 * tq];
                af[2] = *(const unsigned*)&osgs[r0 * OSTR + kc * 16 + 2 * tq + 8];
                af[3] = *(const unsigned*)&osgs[(r0 + 8) * OSTR + kc * 16 + 2 * tq + 8];
                mma_bf16(c, af, wf[kc]);
            }
            int tokA = t0 + r0, tokB = t0 + r0 + 8;
            float2 vA = make_float2(toks[r0 * TSTR + c0] + gm0 * (c[0] + b20),
                                    toks[r0 * TSTR + c0 + 1] + gm1 * (c[1] + b21));
            float2 vB = make_float2(toks[(r0 + 8) * TSTR + c0] + gm0 * (c[2] + b20),
                                    toks[(r0 + 8) * TSTR + c0 + 1] + gm1 * (c[3] + b21));
            *(float2*)&out[x_off(tokA, c0)] = vA;
            *(float2*)&out[x_off(tokB, c0)] = vB;
        }
    }
}

extern "C" void kernel_launch(void* const* d_in, const int* in_sizes, int n_in,
                              void* d_out, int out_size) {
    const float* x     = (const float*)d_in[0];
    const float* ln1_s = (const float*)d_in[1];
    const float* ln1_b = (const float*)d_in[2];
    const float* Wq    = (const float*)d_in[3];
    const float* Wkv   = (const float*)d_in[4];
    const float* bkv   = (const float*)d_in[5];
    const float* Wo    = (const float*)d_in[6];
    const float* bo    = (const float*)d_in[7];
    const float* gamma = (const float*)d_in[8];
    const float* ln2s  = (const float*)d_in[9];
    const float* ln2b  = (const float*)d_in[10];
    const float* W1    = (const float*)d_in[11];
    const float* b1    = (const float*)d_in[12];
    const float* W2    = (const float*)d_in[13];
    const float* b2    = (const float*)d_in[14];
    const float* gmlp  = (const float*)d_in[15];
    float* out = (float*)d_out;

    static int epi_cfg = 0;
    if (!epi_cfg) {
        cudaFuncSetAttribute(k_epi, cudaFuncAttributeMaxDynamicSharedMemorySize, EPI_SMEM);
        epi_cfg = 1;
    }

    k_prep  <<<192, 256>>>(Wq, Wkv, Wo, W1, W2);
    k_lnproj<<<NTOK / 128, 256>>>(x, ln1_s, ln1_b, bkv);
    k_attn  <<<NWIN * NHEAD, 128>>>(bkv);
    k_epi   <<<NTOK / 128, 512, EPI_SMEM>>>(x, bo, gamma, ln2s, ln2b, b1, b2, gmlp, out);
}